// round 15
// baseline (speedup 1.0000x reference)
#include <cuda_runtime.h>
#include <math.h>

#define N_NODES 100000
#define N_EDGES 1000000
#define HID 64
#define EDIM 32
#define NSTEPS 4

typedef unsigned long long u64;
typedef unsigned int u32;

__device__ __forceinline__ float fsigmoid(float x) {
    return __fdividef(1.f, 1.f + __expf(-x));
}
__device__ __forceinline__ float ftanh(float x) {
    float e = __expf(-2.f * x);
    return __fdividef(1.f - e, 1.f + e);
}
// ---- tf32 helpers ----
__device__ __forceinline__ u32 f2tf(float f) {
    u32 u; asm("cvt.rna.tf32.f32 %0, %1;" : "=r"(u) : "f"(f)); return u;
}
__device__ __forceinline__ void mma_tf32(float* c, u32 a0, u32 a1, u32 a2, u32 a3,
                                         u32 b0, u32 b1) {
    asm volatile("mma.sync.aligned.m16n8k8.row.col.f32.tf32.tf32.f32 "
        "{%0,%1,%2,%3}, {%4,%5,%6,%7}, {%8,%9}, {%0,%1,%2,%3};"
        : "+f"(c[0]), "+f"(c[1]), "+f"(c[2]), "+f"(c[3])
        : "r"(a0), "r"(a1), "r"(a2), "r"(a3), "r"(b0), "r"(b1));
}

// -------- device scratch --------
__device__ __align__(128) float g_msg[(size_t)N_EDGES * HID];   // 256 MB (CSR-ordered)
__device__ __align__(128) float g_agg[(size_t)N_NODES * HID];   // 25.6 MB
__device__ __align__(128) u32 g_W1frag[4 * 8 * 32 * 2];         // msg layer-1 B-frags
__device__ __align__(128) u32 g_W2frag[8 * 8 * 32 * 2];         // msg layer-2 B-frags
#define GRU_FRAG_U32 (8 * 24 * 32 * 2)                          // 12288
__device__ __align__(128) u32 g_WihFrag[GRU_FRAG_U32];          // gru B-frags (192 out)
__device__ __align__(128) u32 g_WhhFrag[GRU_FRAG_U32];
__device__ __align__(128) int g_count[N_NODES];                 // zeroed by scan after use
__device__ __align__(128) int g_rowstart[N_NODES + 1];
__device__ __align__(128) int g_cursor[N_NODES];
__device__ __align__(128) int g_src[N_EDGES];
__device__ __align__(128) int g_eperm[N_EDGES];

// -------- CSR build: histogram --------
__global__ __launch_bounds__(256) void hist_kernel(const int* __restrict__ eidx) {
    int t = blockIdx.x * 256 + threadIdx.x;
    if (t >= N_EDGES) return;
    int dst = eidx[t];
    if ((unsigned)dst < N_NODES) atomicAdd(&g_count[dst], 1);
}

// -------- CSR build: scan; builds all tf32 weight fragments; re-zeroes g_count
__global__ __launch_bounds__(1024) void scan_kernel(
    const float* __restrict__ W1, const float* __restrict__ W2,
    const float* __restrict__ Wih, const float* __restrict__ Whh)
{
    // B-frag layout (m16n8k8, row.col): lane = g*4+t; b0 = (k = kk*8+t, n = nt*8+g),
    // b1 = same with k+4. Stored at [((kk*NT + nt)*32 + lane)*2 + {0,1}].
    {
        int p = threadIdx.x;                 // 1024 = 4 kk * 8 nt * 32 lanes
        int lane = p & 31, nt = (p >> 5) & 7, kk = p >> 8;
        int gg = lane >> 2, tt = lane & 3;
        int n = nt * 8 + gg;
        g_W1frag[p * 2]     = f2tf(W1[n * EDIM + kk * 8 + tt]);
        g_W1frag[p * 2 + 1] = f2tf(W1[n * EDIM + kk * 8 + tt + 4]);
    }
    for (int p = threadIdx.x; p < 2048; p += 1024) {             // 8 kk * 8 nt * 32
        int lane = p & 31, nt = (p >> 5) & 7, kk = p >> 8;
        int gg = lane >> 2, tt = lane & 3;
        int n = nt * 8 + gg;
        g_W2frag[p * 2]     = f2tf(W2[n * HID + kk * 8 + tt]);
        g_W2frag[p * 2 + 1] = f2tf(W2[n * HID + kk * 8 + tt + 4]);
    }
    for (int p = threadIdx.x; p < 6144; p += 1024) {             // 8 kk * 24 nt * 32
        int lane = p & 31;
        int knt = p >> 5;                    // kk*24 + nt
        int kk = knt / 24, nt = knt % 24;
        int gg = lane >> 2, tt = lane & 3;
        int n = nt * 8 + gg;                 // 0..191
        g_WihFrag[p * 2]     = f2tf(Wih[n * HID + kk * 8 + tt]);
        g_WihFrag[p * 2 + 1] = f2tf(Wih[n * HID + kk * 8 + tt + 4]);
        g_WhhFrag[p * 2]     = f2tf(Whh[n * HID + kk * 8 + tt]);
        g_WhhFrag[p * 2 + 1] = f2tf(Whh[n * HID + kk * 8 + tt + 4]);
    }

    __shared__ int s[1024];
    const int T = 1024;
    const int tid = threadIdx.x;
    const int chunk = (N_NODES + T - 1) / T;
    const int start = tid * chunk;
    int sum = 0;
    for (int i = 0; i < chunk; ++i) {
        int idx = start + i;
        if (idx < N_NODES) sum += g_count[idx];
    }
    s[tid] = sum;
    __syncthreads();
    for (int off = 1; off < T; off <<= 1) {
        int v = 0;
        if (tid >= off) v = s[tid - off];
        __syncthreads();
        if (tid >= off) s[tid] += v;
        __syncthreads();
    }
    int run = (tid == 0) ? 0 : s[tid - 1];
    for (int i = 0; i < chunk; ++i) {
        int idx = start + i;
        if (idx < N_NODES) {
            g_rowstart[idx] = run;
            g_cursor[idx]   = run;
            run += g_count[idx];
            g_count[idx] = 0;
        }
    }
    if (tid == T - 1) g_rowstart[N_NODES] = run;
}

// -------- CSR build: bucket placement --------
__global__ __launch_bounds__(256) void place_kernel(const int* __restrict__ eidx) {
    int t = blockIdx.x * 256 + threadIdx.x;
    if (t >= N_EDGES) return;
    int dst = eidx[t];
    int src = eidx[N_EDGES + t];
    if ((unsigned)dst >= N_NODES || (unsigned)src >= N_NODES) { g_eperm[t] = 0; return; }
    int pos = atomicAdd(&g_cursor[dst], 1);
    g_src[pos] = src;
    g_eperm[t] = pos;
}

// -------- K1: msg MLP via tf32 mma.sync (R13 winner, unchanged) --------------
#define MSG_PITCH 68
#define MSG_SMEM_WORDS (256 * MSG_PITCH + 2048 + 4096)
#define MSG_SMEM_BYTES (MSG_SMEM_WORDS * 4)   // 94,208 B -> 2 CTAs/SM

__global__ __launch_bounds__(256, 2) void msg_kernel(
    const float* __restrict__ ea,
    const float* __restrict__ b1, const float* __restrict__ b2)
{
    extern __shared__ u32 smu[];
    u32* hidS = smu;
    u32* f1   = smu + 256 * MSG_PITCH;
    u32* f2   = f1 + 2048;

    const int tid = threadIdx.x;
    const int w = tid >> 5;
    const int lane = tid & 31;
    const int g = lane >> 2, t = lane & 3;
    const int eb = blockIdx.x * 256;

    for (int i = tid; i < 2048; i += 256) f1[i] = g_W1frag[i];
    for (int i = tid; i < 4096; i += 256) f2[i] = g_W2frag[i];
    __syncthreads();

    const int ebase = eb + w * 32;

    #pragma unroll 1
    for (int m = 0; m < 2; ++m) {
        const int e0 = ebase + m * 16;
        const int r0 = e0 + g, r1 = e0 + g + 8;
        const int lr0 = w * 32 + m * 16 + g, lr1 = lr0 + 8;
        float c[8][4];

        #pragma unroll
        for (int nt = 0; nt < 8; ++nt) {
            float blo = __ldg(&b1[nt * 8 + 2 * t]);
            float bhi = __ldg(&b1[nt * 8 + 2 * t + 1]);
            c[nt][0] = blo; c[nt][1] = bhi; c[nt][2] = blo; c[nt][3] = bhi;
        }
        #pragma unroll
        for (int kk = 0; kk < 4; ++kk) {
            float fa0 = (r0 < N_EDGES) ? __ldg(&ea[(size_t)r0 * EDIM + kk * 8 + t])     : 0.f;
            float fa1 = (r1 < N_EDGES) ? __ldg(&ea[(size_t)r1 * EDIM + kk * 8 + t])     : 0.f;
            float fa2 = (r0 < N_EDGES) ? __ldg(&ea[(size_t)r0 * EDIM + kk * 8 + t + 4]) : 0.f;
            float fa3 = (r1 < N_EDGES) ? __ldg(&ea[(size_t)r1 * EDIM + kk * 8 + t + 4]) : 0.f;
            u32 a0 = f2tf(fa0), a1 = f2tf(fa1), a2 = f2tf(fa2), a3 = f2tf(fa3);
            #pragma unroll
            for (int nt = 0; nt < 8; ++nt) {
                uint2 b = *reinterpret_cast<const uint2*>(&f1[((kk * 8 + nt) * 32 + lane) * 2]);
                mma_tf32(c[nt], a0, a1, a2, a3, b.x, b.y);
            }
        }
        #pragma unroll
        for (int nt = 0; nt < 8; ++nt) {
            u32 v00 = f2tf(fmaxf(c[nt][0], 0.f)), v01 = f2tf(fmaxf(c[nt][1], 0.f));
            u32 v10 = f2tf(fmaxf(c[nt][2], 0.f)), v11 = f2tf(fmaxf(c[nt][3], 0.f));
            *reinterpret_cast<uint2*>(&hidS[lr0 * MSG_PITCH + nt * 8 + 2 * t]) = make_uint2(v00, v01);
            *reinterpret_cast<uint2*>(&hidS[lr1 * MSG_PITCH + nt * 8 + 2 * t]) = make_uint2(v10, v11);
        }
        __syncwarp();

        #pragma unroll
        for (int nt = 0; nt < 8; ++nt) {
            float blo = __ldg(&b2[nt * 8 + 2 * t]);
            float bhi = __ldg(&b2[nt * 8 + 2 * t + 1]);
            c[nt][0] = blo; c[nt][1] = bhi; c[nt][2] = blo; c[nt][3] = bhi;
        }
        #pragma unroll
        for (int kk = 0; kk < 8; ++kk) {
            u32 a0 = hidS[lr0 * MSG_PITCH + kk * 8 + t];
            u32 a1 = hidS[lr1 * MSG_PITCH + kk * 8 + t];
            u32 a2 = hidS[lr0 * MSG_PITCH + kk * 8 + t + 4];
            u32 a3 = hidS[lr1 * MSG_PITCH + kk * 8 + t + 4];
            #pragma unroll
            for (int nt = 0; nt < 8; ++nt) {
                uint2 b = *reinterpret_cast<const uint2*>(&f2[((kk * 8 + nt) * 32 + lane) * 2]);
                mma_tf32(c[nt], a0, a1, a2, a3, b.x, b.y);
            }
        }
        int slot0 = (r0 < N_EDGES) ? __ldg(&g_eperm[r0]) : 0;
        int slot1 = (r1 < N_EDGES) ? __ldg(&g_eperm[r1]) : 0;
        #pragma unroll
        for (int nt = 0; nt < 8; ++nt) {
            if (r0 < N_EDGES)
                *reinterpret_cast<float2*>(&g_msg[(size_t)slot0 * HID + nt * 8 + 2 * t]) =
                    make_float2(c[nt][0], c[nt][1]);
            if (r1 < N_EDGES)
                *reinterpret_cast<float2*>(&g_msg[(size_t)slot1 * HID + nt * 8 + 2 * t]) =
                    make_float2(c[nt][2], c[nt][3]);
        }
        __syncwarp();
    }
}

// -------- K2: gather aggregation; 4-way unroll (MLP=8) + shuffled src --------
__global__ __launch_bounds__(256) void gather_kernel(const float* __restrict__ h) {
    int t = blockIdx.x * 256 + threadIdx.x;
    int n = t >> 4;
    int q = t & 15;
    if (n >= N_NODES) return;
    int p  = g_rowstart[n];
    int re = g_rowstart[n + 1];
    // half-warp shuffle mask: lanes 0-15 -> 0x0000ffff, lanes 16-31 -> 0xffff0000
    const unsigned hm = 0xffffu << (threadIdx.x & 16);
    float4 acc = make_float4(0.f, 0.f, 0.f, 0.f);

    for (; p + 3 < re; p += 4) {
        int sv = 0;
        if (q < 4) sv = __ldg(&g_src[p + q]);
        int s0 = __shfl_sync(hm, sv, 0, 16);
        int s1 = __shfl_sync(hm, sv, 1, 16);
        int s2 = __shfl_sync(hm, sv, 2, 16);
        int s3 = __shfl_sync(hm, sv, 3, 16);
        float4 m0 = __ldcs(reinterpret_cast<const float4*>(&g_msg[(size_t)(p + 0) * HID + q * 4]));
        float4 m1 = __ldcs(reinterpret_cast<const float4*>(&g_msg[(size_t)(p + 1) * HID + q * 4]));
        float4 m2 = __ldcs(reinterpret_cast<const float4*>(&g_msg[(size_t)(p + 2) * HID + q * 4]));
        float4 m3 = __ldcs(reinterpret_cast<const float4*>(&g_msg[(size_t)(p + 3) * HID + q * 4]));
        float4 h0 = __ldg(reinterpret_cast<const float4*>(&h[(size_t)s0 * HID + q * 4]));
        float4 h1 = __ldg(reinterpret_cast<const float4*>(&h[(size_t)s1 * HID + q * 4]));
        float4 h2 = __ldg(reinterpret_cast<const float4*>(&h[(size_t)s2 * HID + q * 4]));
        float4 h3 = __ldg(reinterpret_cast<const float4*>(&h[(size_t)s3 * HID + q * 4]));
        acc.x += m0.x * h0.x; acc.y += m0.y * h0.y; acc.z += m0.z * h0.z; acc.w += m0.w * h0.w;
        acc.x += m1.x * h1.x; acc.y += m1.y * h1.y; acc.z += m1.z * h1.z; acc.w += m1.w * h1.w;
        acc.x += m2.x * h2.x; acc.y += m2.y * h2.y; acc.z += m2.z * h2.z; acc.w += m2.w * h2.w;
        acc.x += m3.x * h3.x; acc.y += m3.y * h3.y; acc.z += m3.z * h3.z; acc.w += m3.w * h3.w;
    }
    for (; p < re; ++p) {
        float4 m = __ldcs(reinterpret_cast<const float4*>(&g_msg[(size_t)p * HID + q * 4]));
        int s = __ldg(&g_src[p]);
        float4 hv = __ldg(reinterpret_cast<const float4*>(&h[(size_t)s * HID + q * 4]));
        acc.x += m.x * hv.x; acc.y += m.y * hv.y; acc.z += m.z * hv.z; acc.w += m.w * hv.w;
    }
    *reinterpret_cast<float4*>(&g_agg[(size_t)n * HID + q * 4]) = acc;
}

// -------- K3: GRU via tf32 mma with A-residual compensation (R14 winner) -----
#define GP 196
#define GRU_SMEM_BYTES (2 * GRU_FRAG_U32 * 4 + 2 * 64 * GP * 4)   // 198,656 B

__global__ __launch_bounds__(512) void gru_kernel(
    const float* __restrict__ bih, const float* __restrict__ bhh,
    float* __restrict__ h)
{
    extern __shared__ u32 smu[];
    u32* fIH = smu;
    u32* fHH = smu + GRU_FRAG_U32;
    float* sGi = reinterpret_cast<float*>(smu + 2 * GRU_FRAG_U32);  // [64][GP]
    float* sGh = sGi + 64 * GP;

    const int tid = threadIdx.x;
    const int w = tid >> 5;
    const int lane = tid & 31;
    const int g = lane >> 2, t = lane & 3;
    const int m = w & 3;         // m-tile (16 nodes)
    const int nh = w >> 2;       // output group (6 nt)
    const int d = tid & 63;      // epilogue dim

    for (int i = tid; i < GRU_FRAG_U32; i += 512) { fIH[i] = g_WihFrag[i]; fHH[i] = g_WhhFrag[i]; }
    const float bi_r = __ldg(&bih[d]), bi_z = __ldg(&bih[64 + d]), bi_n = __ldg(&bih[128 + d]);
    const float bh_r = __ldg(&bhh[d]), bh_z = __ldg(&bhh[64 + d]), bh_n = __ldg(&bhh[128 + d]);
    __syncthreads();

    const int ntiles = (N_NODES + 63) / 64;   // 1563
    for (int tile = blockIdx.x; tile < ntiles; tile += gridDim.x) {
        const int nb = tile * 64;
        const int r0 = nb + m * 16 + g, r1 = r0 + 8;
        const bool v0 = r0 < N_NODES, v1 = r1 < N_NODES;

        // ---- GEMM1: Gi = agg x Wih^T ----
        float c[6][4];
        #pragma unroll
        for (int j = 0; j < 6; ++j) { c[j][0] = c[j][1] = c[j][2] = c[j][3] = 0.f; }
        #pragma unroll
        for (int kk = 0; kk < 8; ++kk) {
            float fa0 = v0 ? __ldg(&g_agg[(size_t)r0 * HID + kk * 8 + t])     : 0.f;
            float fa1 = v1 ? __ldg(&g_agg[(size_t)r1 * HID + kk * 8 + t])     : 0.f;
            float fa2 = v0 ? __ldg(&g_agg[(size_t)r0 * HID + kk * 8 + t + 4]) : 0.f;
            float fa3 = v1 ? __ldg(&g_agg[(size_t)r1 * HID + kk * 8 + t + 4]) : 0.f;
            u32 A0 = f2tf(fa0), A1 = f2tf(fa1), A2 = f2tf(fa2), A3 = f2tf(fa3);
            u32 S0 = f2tf(fa0 - __uint_as_float(A0));
            u32 S1 = f2tf(fa1 - __uint_as_float(A1));
            u32 S2 = f2tf(fa2 - __uint_as_float(A2));
            u32 S3 = f2tf(fa3 - __uint_as_float(A3));
            #pragma unroll
            for (int j = 0; j < 6; ++j) {
                uint2 b = *reinterpret_cast<const uint2*>(&fIH[((kk * 24 + nh * 6 + j) * 32 + lane) * 2]);
                mma_tf32(c[j], A0, A1, A2, A3, b.x, b.y);
                mma_tf32(c[j], S0, S1, S2, S3, b.x, b.y);
            }
        }
        #pragma unroll
        for (int j = 0; j < 6; ++j) {
            int n8 = (nh * 6 + j) * 8 + 2 * t;
            *reinterpret_cast<float2*>(&sGi[(m * 16 + g) * GP + n8])     = make_float2(c[j][0], c[j][1]);
            *reinterpret_cast<float2*>(&sGi[(m * 16 + g + 8) * GP + n8]) = make_float2(c[j][2], c[j][3]);
        }

        // ---- GEMM2: Gh = h x Whh^T ----
        #pragma unroll
        for (int j = 0; j < 6; ++j) { c[j][0] = c[j][1] = c[j][2] = c[j][3] = 0.f; }
        #pragma unroll
        for (int kk = 0; kk < 8; ++kk) {
            float fa0 = v0 ? __ldg(&h[(size_t)r0 * HID + kk * 8 + t])     : 0.f;
            float fa1 = v1 ? __ldg(&h[(size_t)r1 * HID + kk * 8 + t])     : 0.f;
            float fa2 = v0 ? __ldg(&h[(size_t)r0 * HID + kk * 8 + t + 4]) : 0.f;
            float fa3 = v1 ? __ldg(&h[(size_t)r1 * HID + kk * 8 + t + 4]) : 0.f;
            u32 A0 = f2tf(fa0), A1 = f2tf(fa1), A2 = f2tf(fa2), A3 = f2tf(fa3);
            u32 S0 = f2tf(fa0 - __uint_as_float(A0));
            u32 S1 = f2tf(fa1 - __uint_as_float(A1));
            u32 S2 = f2tf(fa2 - __uint_as_float(A2));
            u32 S3 = f2tf(fa3 - __uint_as_float(A3));
            #pragma unroll
            for (int j = 0; j < 6; ++j) {
                uint2 b = *reinterpret_cast<const uint2*>(&fHH[((kk * 24 + nh * 6 + j) * 32 + lane) * 2]);
                mma_tf32(c[j], A0, A1, A2, A3, b.x, b.y);
                mma_tf32(c[j], S0, S1, S2, S3, b.x, b.y);
            }
        }
        #pragma unroll
        for (int j = 0; j < 6; ++j) {
            int n8 = (nh * 6 + j) * 8 + 2 * t;
            *reinterpret_cast<float2*>(&sGh[(m * 16 + g) * GP + n8])     = make_float2(c[j][0], c[j][1]);
            *reinterpret_cast<float2*>(&sGh[(m * 16 + g + 8) * GP + n8]) = make_float2(c[j][2], c[j][3]);
        }
        __syncthreads();

        // ---- epilogue: elementwise GRU, coalesced ----
        #pragma unroll
        for (int it = 0; it < 8; ++it) {
            int node = it * 8 + (tid >> 6);
            if (nb + node < N_NODES) {
                float ir = sGi[node * GP + d];
                float iz = sGi[node * GP + 64 + d];
                float in_ = sGi[node * GP + 128 + d];
                float hr = sGh[node * GP + d];
                float hz = sGh[node * GP + 64 + d];
                float hn = sGh[node * GP + 128 + d];
                float rv = fsigmoid(ir + hr + bi_r + bh_r);
                float zv = fsigmoid(iz + hz + bi_z + bh_z);
                float nn = ftanh(in_ + bi_n + rv * (hn + bh_n));
                float hp = h[(size_t)(nb + node) * HID + d];
                h[(size_t)(nb + node) * HID + d] = (1.f - zv) * nn + zv * hp;
            }
        }
        __syncthreads();
    }
}

// -------- launch --------
extern "C" void kernel_launch(void* const* d_in, const int* in_sizes, int n_in,
                              void* d_out, int out_size)
{
    const float* h0   = (const float*)d_in[0];
    const float* ea   = (const float*)d_in[1];
    const int*   eidx = (const int*)d_in[2];     // int64 inputs arrive as int32
    const float* W1   = (const float*)d_in[3];
    const float* b1   = (const float*)d_in[4];
    const float* W2   = (const float*)d_in[5];
    const float* b2   = (const float*)d_in[6];
    const float* Wih  = (const float*)d_in[7];
    const float* bih  = (const float*)d_in[8];
    const float* Whh  = (const float*)d_in[9];
    const float* bhh  = (const float*)d_in[10];
    float* h = (float*)d_out;

    cudaFuncSetAttribute(gru_kernel, cudaFuncAttributeMaxDynamicSharedMemorySize,
                         GRU_SMEM_BYTES);
    cudaFuncSetAttribute(msg_kernel, cudaFuncAttributeMaxDynamicSharedMemorySize,
                         MSG_SMEM_BYTES);

    cudaMemcpyAsync(h, h0, (size_t)N_NODES * HID * sizeof(float),
                    cudaMemcpyDeviceToDevice, 0);

    // CSR build; g_count re-zeroed inside scan_kernel
    hist_kernel<<<(N_EDGES + 255) / 256, 256>>>(eidx);
    scan_kernel<<<1, 1024>>>(W1, W2, Wih, Whh);
    place_kernel<<<(N_EDGES + 255) / 256, 256>>>(eidx);

    msg_kernel<<<(N_EDGES + 255) / 256, 256, MSG_SMEM_BYTES>>>(ea, b1, b2);

    for (int s = 0; s < NSTEPS; ++s) {
        gather_kernel<<<(N_NODES * 16 + 255) / 256, 256>>>(h);
        gru_kernel<<<152, 512, GRU_SMEM_BYTES>>>(bih, bhh, h);
    }
}

// round 16
// speedup vs baseline: 1.0472x; 1.0472x over previous
#include <cuda_runtime.h>
#include <math.h>

#define N_NODES 100000
#define N_EDGES 1000000
#define HID 64
#define EDIM 32
#define NSTEPS 4

typedef unsigned long long u64;
typedef unsigned int u32;

__device__ __forceinline__ float fsigmoid(float x) {
    return __fdividef(1.f, 1.f + __expf(-x));
}
__device__ __forceinline__ float ftanh(float x) {
    float e = __expf(-2.f * x);
    return __fdividef(1.f - e, 1.f + e);
}
// ---- tf32 helpers ----
__device__ __forceinline__ u32 f2tf(float f) {
    u32 u; asm("cvt.rna.tf32.f32 %0, %1;" : "=r"(u) : "f"(f)); return u;
}
__device__ __forceinline__ void mma_tf32(float* c, u32 a0, u32 a1, u32 a2, u32 a3,
                                         u32 b0, u32 b1) {
    asm volatile("mma.sync.aligned.m16n8k8.row.col.f32.tf32.tf32.f32 "
        "{%0,%1,%2,%3}, {%4,%5,%6,%7}, {%8,%9}, {%0,%1,%2,%3};"
        : "+f"(c[0]), "+f"(c[1]), "+f"(c[2]), "+f"(c[3])
        : "r"(a0), "r"(a1), "r"(a2), "r"(a3), "r"(b0), "r"(b1));
}

// -------- device scratch --------
__device__ __align__(128) float g_msg[(size_t)N_EDGES * HID];   // 256 MB (CSR-ordered)
__device__ __align__(128) float g_agg[(size_t)N_NODES * HID];   // 25.6 MB
__device__ __align__(128) u32 g_W1frag[4 * 8 * 32 * 2];         // msg layer-1 B-frags
__device__ __align__(128) u32 g_W2frag[8 * 8 * 32 * 2];         // msg layer-2 B-frags
#define GRU_FRAG_U32 (8 * 24 * 32 * 2)                          // 12288
__device__ __align__(128) u32 g_WihFrag[GRU_FRAG_U32];          // gru B-frags (192 out)
__device__ __align__(128) u32 g_WhhFrag[GRU_FRAG_U32];
__device__ __align__(128) int g_count[N_NODES];                 // zeroed by scan after use
__device__ __align__(128) int g_rowstart[N_NODES + 1];
__device__ __align__(128) int g_cursor[N_NODES];
__device__ __align__(128) int g_src[N_EDGES];
__device__ __align__(128) int g_eperm[N_EDGES];

// -------- CSR build: histogram --------
__global__ __launch_bounds__(256) void hist_kernel(const int* __restrict__ eidx) {
    int t = blockIdx.x * 256 + threadIdx.x;
    if (t >= N_EDGES) return;
    int dst = eidx[t];
    if ((unsigned)dst < N_NODES) atomicAdd(&g_count[dst], 1);
}

// -------- CSR build: scan; builds all tf32 weight fragments; re-zeroes g_count
__global__ __launch_bounds__(1024) void scan_kernel(
    const float* __restrict__ W1, const float* __restrict__ W2,
    const float* __restrict__ Wih, const float* __restrict__ Whh)
{
    // B-frag layout (m16n8k8, row.col): lane = g*4+t; b0 = (k = kk*8+t, n = nt*8+g),
    // b1 = same with k+4. Stored at [((kk*NT + nt)*32 + lane)*2 + {0,1}].
    {
        int p = threadIdx.x;                 // 1024 = 4 kk * 8 nt * 32 lanes
        int lane = p & 31, nt = (p >> 5) & 7, kk = p >> 8;
        int gg = lane >> 2, tt = lane & 3;
        int n = nt * 8 + gg;
        g_W1frag[p * 2]     = f2tf(W1[n * EDIM + kk * 8 + tt]);
        g_W1frag[p * 2 + 1] = f2tf(W1[n * EDIM + kk * 8 + tt + 4]);
    }
    for (int p = threadIdx.x; p < 2048; p += 1024) {             // 8 kk * 8 nt * 32
        int lane = p & 31, nt = (p >> 5) & 7, kk = p >> 8;
        int gg = lane >> 2, tt = lane & 3;
        int n = nt * 8 + gg;
        g_W2frag[p * 2]     = f2tf(W2[n * HID + kk * 8 + tt]);
        g_W2frag[p * 2 + 1] = f2tf(W2[n * HID + kk * 8 + tt + 4]);
    }
    for (int p = threadIdx.x; p < 6144; p += 1024) {             // 8 kk * 24 nt * 32
        int lane = p & 31;
        int knt = p >> 5;                    // kk*24 + nt
        int kk = knt / 24, nt = knt % 24;
        int gg = lane >> 2, tt = lane & 3;
        int n = nt * 8 + gg;                 // 0..191
        g_WihFrag[p * 2]     = f2tf(Wih[n * HID + kk * 8 + tt]);
        g_WihFrag[p * 2 + 1] = f2tf(Wih[n * HID + kk * 8 + tt + 4]);
        g_WhhFrag[p * 2]     = f2tf(Whh[n * HID + kk * 8 + tt]);
        g_WhhFrag[p * 2 + 1] = f2tf(Whh[n * HID + kk * 8 + tt + 4]);
    }

    __shared__ int s[1024];
    const int T = 1024;
    const int tid = threadIdx.x;
    const int chunk = (N_NODES + T - 1) / T;
    const int start = tid * chunk;
    int sum = 0;
    for (int i = 0; i < chunk; ++i) {
        int idx = start + i;
        if (idx < N_NODES) sum += g_count[idx];
    }
    s[tid] = sum;
    __syncthreads();
    for (int off = 1; off < T; off <<= 1) {
        int v = 0;
        if (tid >= off) v = s[tid - off];
        __syncthreads();
        if (tid >= off) s[tid] += v;
        __syncthreads();
    }
    int run = (tid == 0) ? 0 : s[tid - 1];
    for (int i = 0; i < chunk; ++i) {
        int idx = start + i;
        if (idx < N_NODES) {
            g_rowstart[idx] = run;
            g_cursor[idx]   = run;
            run += g_count[idx];
            g_count[idx] = 0;
        }
    }
    if (tid == T - 1) g_rowstart[N_NODES] = run;
}

// -------- CSR build: bucket placement --------
__global__ __launch_bounds__(256) void place_kernel(const int* __restrict__ eidx) {
    int t = blockIdx.x * 256 + threadIdx.x;
    if (t >= N_EDGES) return;
    int dst = eidx[t];
    int src = eidx[N_EDGES + t];
    if ((unsigned)dst >= N_NODES || (unsigned)src >= N_NODES) { g_eperm[t] = 0; return; }
    int pos = atomicAdd(&g_cursor[dst], 1);
    g_src[pos] = src;
    g_eperm[t] = pos;
}

// -------- K1: msg MLP via tf32 mma.sync (R13 winner, unchanged) --------------
#define MSG_PITCH 68
#define MSG_SMEM_WORDS (256 * MSG_PITCH + 2048 + 4096)
#define MSG_SMEM_BYTES (MSG_SMEM_WORDS * 4)   // 94,208 B -> 2 CTAs/SM

__global__ __launch_bounds__(256, 2) void msg_kernel(
    const float* __restrict__ ea,
    const float* __restrict__ b1, const float* __restrict__ b2)
{
    extern __shared__ u32 smu[];
    u32* hidS = smu;
    u32* f1   = smu + 256 * MSG_PITCH;
    u32* f2   = f1 + 2048;

    const int tid = threadIdx.x;
    const int w = tid >> 5;
    const int lane = tid & 31;
    const int g = lane >> 2, t = lane & 3;
    const int eb = blockIdx.x * 256;

    for (int i = tid; i < 2048; i += 256) f1[i] = g_W1frag[i];
    for (int i = tid; i < 4096; i += 256) f2[i] = g_W2frag[i];
    __syncthreads();

    const int ebase = eb + w * 32;

    #pragma unroll 1
    for (int m = 0; m < 2; ++m) {
        const int e0 = ebase + m * 16;
        const int r0 = e0 + g, r1 = e0 + g + 8;
        const int lr0 = w * 32 + m * 16 + g, lr1 = lr0 + 8;
        float c[8][4];

        #pragma unroll
        for (int nt = 0; nt < 8; ++nt) {
            float blo = __ldg(&b1[nt * 8 + 2 * t]);
            float bhi = __ldg(&b1[nt * 8 + 2 * t + 1]);
            c[nt][0] = blo; c[nt][1] = bhi; c[nt][2] = blo; c[nt][3] = bhi;
        }
        #pragma unroll
        for (int kk = 0; kk < 4; ++kk) {
            float fa0 = (r0 < N_EDGES) ? __ldg(&ea[(size_t)r0 * EDIM + kk * 8 + t])     : 0.f;
            float fa1 = (r1 < N_EDGES) ? __ldg(&ea[(size_t)r1 * EDIM + kk * 8 + t])     : 0.f;
            float fa2 = (r0 < N_EDGES) ? __ldg(&ea[(size_t)r0 * EDIM + kk * 8 + t + 4]) : 0.f;
            float fa3 = (r1 < N_EDGES) ? __ldg(&ea[(size_t)r1 * EDIM + kk * 8 + t + 4]) : 0.f;
            u32 a0 = f2tf(fa0), a1 = f2tf(fa1), a2 = f2tf(fa2), a3 = f2tf(fa3);
            #pragma unroll
            for (int nt = 0; nt < 8; ++nt) {
                uint2 b = *reinterpret_cast<const uint2*>(&f1[((kk * 8 + nt) * 32 + lane) * 2]);
                mma_tf32(c[nt], a0, a1, a2, a3, b.x, b.y);
            }
        }
        #pragma unroll
        for (int nt = 0; nt < 8; ++nt) {
            u32 v00 = f2tf(fmaxf(c[nt][0], 0.f)), v01 = f2tf(fmaxf(c[nt][1], 0.f));
            u32 v10 = f2tf(fmaxf(c[nt][2], 0.f)), v11 = f2tf(fmaxf(c[nt][3], 0.f));
            *reinterpret_cast<uint2*>(&hidS[lr0 * MSG_PITCH + nt * 8 + 2 * t]) = make_uint2(v00, v01);
            *reinterpret_cast<uint2*>(&hidS[lr1 * MSG_PITCH + nt * 8 + 2 * t]) = make_uint2(v10, v11);
        }
        __syncwarp();

        #pragma unroll
        for (int nt = 0; nt < 8; ++nt) {
            float blo = __ldg(&b2[nt * 8 + 2 * t]);
            float bhi = __ldg(&b2[nt * 8 + 2 * t + 1]);
            c[nt][0] = blo; c[nt][1] = bhi; c[nt][2] = blo; c[nt][3] = bhi;
        }
        #pragma unroll
        for (int kk = 0; kk < 8; ++kk) {
            u32 a0 = hidS[lr0 * MSG_PITCH + kk * 8 + t];
            u32 a1 = hidS[lr1 * MSG_PITCH + kk * 8 + t];
            u32 a2 = hidS[lr0 * MSG_PITCH + kk * 8 + t + 4];
            u32 a3 = hidS[lr1 * MSG_PITCH + kk * 8 + t + 4];
            #pragma unroll
            for (int nt = 0; nt < 8; ++nt) {
                uint2 b = *reinterpret_cast<const uint2*>(&f2[((kk * 8 + nt) * 32 + lane) * 2]);
                mma_tf32(c[nt], a0, a1, a2, a3, b.x, b.y);
            }
        }
        int slot0 = (r0 < N_EDGES) ? __ldg(&g_eperm[r0]) : 0;
        int slot1 = (r1 < N_EDGES) ? __ldg(&g_eperm[r1]) : 0;
        #pragma unroll
        for (int nt = 0; nt < 8; ++nt) {
            if (r0 < N_EDGES)
                *reinterpret_cast<float2*>(&g_msg[(size_t)slot0 * HID + nt * 8 + 2 * t]) =
                    make_float2(c[nt][0], c[nt][1]);
            if (r1 < N_EDGES)
                *reinterpret_cast<float2*>(&g_msg[(size_t)slot1 * HID + nt * 8 + 2 * t]) =
                    make_float2(c[nt][2], c[nt][3]);
        }
        __syncwarp();
    }
}

// -------- K2: gather; 8 threads/node (32 B/lane), 2-edge unroll, MLP=8 -------
__global__ __launch_bounds__(256) void gather_kernel(const float* __restrict__ h) {
    int t = blockIdx.x * 256 + threadIdx.x;
    int n = t >> 3;
    int q = t & 7;                 // lane owns floats [q*8, q*8+8)
    if (n >= N_NODES) return;
    int p  = g_rowstart[n];
    int re = g_rowstart[n + 1];
    float4 accA = make_float4(0.f, 0.f, 0.f, 0.f);
    float4 accB = make_float4(0.f, 0.f, 0.f, 0.f);

    for (; p + 1 < re; p += 2) {
        int s0 = __ldg(&g_src[p]);
        int s1 = __ldg(&g_src[p + 1]);
        const float4* mp0 = reinterpret_cast<const float4*>(&g_msg[(size_t)p * HID + q * 8]);
        const float4* mp1 = reinterpret_cast<const float4*>(&g_msg[(size_t)(p + 1) * HID + q * 8]);
        float4 ma0 = __ldcs(mp0),     mb0 = __ldcs(mp0 + 1);
        float4 ma1 = __ldcs(mp1),     mb1 = __ldcs(mp1 + 1);
        const float4* hp0 = reinterpret_cast<const float4*>(&h[(size_t)s0 * HID + q * 8]);
        const float4* hp1 = reinterpret_cast<const float4*>(&h[(size_t)s1 * HID + q * 8]);
        float4 ha0 = __ldg(hp0),      hb0 = __ldg(hp0 + 1);
        float4 ha1 = __ldg(hp1),      hb1 = __ldg(hp1 + 1);
        accA.x += ma0.x * ha0.x; accA.y += ma0.y * ha0.y; accA.z += ma0.z * ha0.z; accA.w += ma0.w * ha0.w;
        accB.x += mb0.x * hb0.x; accB.y += mb0.y * hb0.y; accB.z += mb0.z * hb0.z; accB.w += mb0.w * hb0.w;
        accA.x += ma1.x * ha1.x; accA.y += ma1.y * ha1.y; accA.z += ma1.z * ha1.z; accA.w += ma1.w * ha1.w;
        accB.x += mb1.x * hb1.x; accB.y += mb1.y * hb1.y; accB.z += mb1.z * hb1.z; accB.w += mb1.w * hb1.w;
    }
    if (p < re) {
        int s = __ldg(&g_src[p]);
        const float4* mp = reinterpret_cast<const float4*>(&g_msg[(size_t)p * HID + q * 8]);
        float4 ma = __ldcs(mp), mb = __ldcs(mp + 1);
        const float4* hp = reinterpret_cast<const float4*>(&h[(size_t)s * HID + q * 8]);
        float4 ha = __ldg(hp), hb = __ldg(hp + 1);
        accA.x += ma.x * ha.x; accA.y += ma.y * ha.y; accA.z += ma.z * ha.z; accA.w += ma.w * ha.w;
        accB.x += mb.x * hb.x; accB.y += mb.y * hb.y; accB.z += mb.z * hb.z; accB.w += mb.w * hb.w;
    }
    float4* op = reinterpret_cast<float4*>(&g_agg[(size_t)n * HID + q * 8]);
    op[0] = accA;
    op[1] = accB;
}

// -------- K3: GRU via tf32 mma with A-residual compensation (R14 winner) -----
#define GP 196
#define GRU_SMEM_BYTES (2 * GRU_FRAG_U32 * 4 + 2 * 64 * GP * 4)   // 198,656 B

__global__ __launch_bounds__(512) void gru_kernel(
    const float* __restrict__ bih, const float* __restrict__ bhh,
    float* __restrict__ h)
{
    extern __shared__ u32 smu[];
    u32* fIH = smu;
    u32* fHH = smu + GRU_FRAG_U32;
    float* sGi = reinterpret_cast<float*>(smu + 2 * GRU_FRAG_U32);  // [64][GP]
    float* sGh = sGi + 64 * GP;

    const int tid = threadIdx.x;
    const int w = tid >> 5;
    const int lane = tid & 31;
    const int g = lane >> 2, t = lane & 3;
    const int m = w & 3;         // m-tile (16 nodes)
    const int nh = w >> 2;       // output group (6 nt)
    const int d = tid & 63;      // epilogue dim

    for (int i = tid; i < GRU_FRAG_U32; i += 512) { fIH[i] = g_WihFrag[i]; fHH[i] = g_WhhFrag[i]; }
    const float bi_r = __ldg(&bih[d]), bi_z = __ldg(&bih[64 + d]), bi_n = __ldg(&bih[128 + d]);
    const float bh_r = __ldg(&bhh[d]), bh_z = __ldg(&bhh[64 + d]), bh_n = __ldg(&bhh[128 + d]);
    __syncthreads();

    const int ntiles = (N_NODES + 63) / 64;   // 1563
    for (int tile = blockIdx.x; tile < ntiles; tile += gridDim.x) {
        const int nb = tile * 64;
        const int r0 = nb + m * 16 + g, r1 = r0 + 8;
        const bool v0 = r0 < N_NODES, v1 = r1 < N_NODES;

        // ---- GEMM1: Gi = agg x Wih^T ----
        float c[6][4];
        #pragma unroll
        for (int j = 0; j < 6; ++j) { c[j][0] = c[j][1] = c[j][2] = c[j][3] = 0.f; }
        #pragma unroll
        for (int kk = 0; kk < 8; ++kk) {
            float fa0 = v0 ? __ldg(&g_agg[(size_t)r0 * HID + kk * 8 + t])     : 0.f;
            float fa1 = v1 ? __ldg(&g_agg[(size_t)r1 * HID + kk * 8 + t])     : 0.f;
            float fa2 = v0 ? __ldg(&g_agg[(size_t)r0 * HID + kk * 8 + t + 4]) : 0.f;
            float fa3 = v1 ? __ldg(&g_agg[(size_t)r1 * HID + kk * 8 + t + 4]) : 0.f;
            u32 A0 = f2tf(fa0), A1 = f2tf(fa1), A2 = f2tf(fa2), A3 = f2tf(fa3);
            u32 S0 = f2tf(fa0 - __uint_as_float(A0));
            u32 S1 = f2tf(fa1 - __uint_as_float(A1));
            u32 S2 = f2tf(fa2 - __uint_as_float(A2));
            u32 S3 = f2tf(fa3 - __uint_as_float(A3));
            #pragma unroll
            for (int j = 0; j < 6; ++j) {
                uint2 b = *reinterpret_cast<const uint2*>(&fIH[((kk * 24 + nh * 6 + j) * 32 + lane) * 2]);
                mma_tf32(c[j], A0, A1, A2, A3, b.x, b.y);
                mma_tf32(c[j], S0, S1, S2, S3, b.x, b.y);
            }
        }
        #pragma unroll
        for (int j = 0; j < 6; ++j) {
            int n8 = (nh * 6 + j) * 8 + 2 * t;
            *reinterpret_cast<float2*>(&sGi[(m * 16 + g) * GP + n8])     = make_float2(c[j][0], c[j][1]);
            *reinterpret_cast<float2*>(&sGi[(m * 16 + g + 8) * GP + n8]) = make_float2(c[j][2], c[j][3]);
        }

        // ---- GEMM2: Gh = h x Whh^T ----
        #pragma unroll
        for (int j = 0; j < 6; ++j) { c[j][0] = c[j][1] = c[j][2] = c[j][3] = 0.f; }
        #pragma unroll
        for (int kk = 0; kk < 8; ++kk) {
            float fa0 = v0 ? __ldg(&h[(size_t)r0 * HID + kk * 8 + t])     : 0.f;
            float fa1 = v1 ? __ldg(&h[(size_t)r1 * HID + kk * 8 + t])     : 0.f;
            float fa2 = v0 ? __ldg(&h[(size_t)r0 * HID + kk * 8 + t + 4]) : 0.f;
            float fa3 = v1 ? __ldg(&h[(size_t)r1 * HID + kk * 8 + t + 4]) : 0.f;
            u32 A0 = f2tf(fa0), A1 = f2tf(fa1), A2 = f2tf(fa2), A3 = f2tf(fa3);
            u32 S0 = f2tf(fa0 - __uint_as_float(A0));
            u32 S1 = f2tf(fa1 - __uint_as_float(A1));
            u32 S2 = f2tf(fa2 - __uint_as_float(A2));
            u32 S3 = f2tf(fa3 - __uint_as_float(A3));
            #pragma unroll
            for (int j = 0; j < 6; ++j) {
                uint2 b = *reinterpret_cast<const uint2*>(&fHH[((kk * 24 + nh * 6 + j) * 32 + lane) * 2]);
                mma_tf32(c[j], A0, A1, A2, A3, b.x, b.y);
                mma_tf32(c[j], S0, S1, S2, S3, b.x, b.y);
            }
        }
        #pragma unroll
        for (int j = 0; j < 6; ++j) {
            int n8 = (nh * 6 + j) * 8 + 2 * t;
            *reinterpret_cast<float2*>(&sGh[(m * 16 + g) * GP + n8])     = make_float2(c[j][0], c[j][1]);
            *reinterpret_cast<float2*>(&sGh[(m * 16 + g + 8) * GP + n8]) = make_float2(c[j][2], c[j][3]);
        }
        __syncthreads();

        // ---- epilogue: elementwise GRU, coalesced ----
        #pragma unroll
        for (int it = 0; it < 8; ++it) {
            int node = it * 8 + (tid >> 6);
            if (nb + node < N_NODES) {
                float ir = sGi[node * GP + d];
                float iz = sGi[node * GP + 64 + d];
                float in_ = sGi[node * GP + 128 + d];
                float hr = sGh[node * GP + d];
                float hz = sGh[node * GP + 64 + d];
                float hn = sGh[node * GP + 128 + d];
                float rv = fsigmoid(ir + hr + bi_r + bh_r);
                float zv = fsigmoid(iz + hz + bi_z + bh_z);
                float nn = ftanh(in_ + bi_n + rv * (hn + bh_n));
                float hp = h[(size_t)(nb + node) * HID + d];
                h[(size_t)(nb + node) * HID + d] = (1.f - zv) * nn + zv * hp;
            }
        }
        __syncthreads();
    }
}

// -------- launch --------
extern "C" void kernel_launch(void* const* d_in, const int* in_sizes, int n_in,
                              void* d_out, int out_size)
{
    const float* h0   = (const float*)d_in[0];
    const float* ea   = (const float*)d_in[1];
    const int*   eidx = (const int*)d_in[2];     // int64 inputs arrive as int32
    const float* W1   = (const float*)d_in[3];
    const float* b1   = (const float*)d_in[4];
    const float* W2   = (const float*)d_in[5];
    const float* b2   = (const float*)d_in[6];
    const float* Wih  = (const float*)d_in[7];
    const float* bih  = (const float*)d_in[8];
    const float* Whh  = (const float*)d_in[9];
    const float* bhh  = (const float*)d_in[10];
    float* h = (float*)d_out;

    cudaFuncSetAttribute(gru_kernel, cudaFuncAttributeMaxDynamicSharedMemorySize,
                         GRU_SMEM_BYTES);
    cudaFuncSetAttribute(msg_kernel, cudaFuncAttributeMaxDynamicSharedMemorySize,
                         MSG_SMEM_BYTES);

    cudaMemcpyAsync(h, h0, (size_t)N_NODES * HID * sizeof(float),
                    cudaMemcpyDeviceToDevice, 0);

    // CSR build; g_count re-zeroed inside scan_kernel
    hist_kernel<<<(N_EDGES + 255) / 256, 256>>>(eidx);
    scan_kernel<<<1, 1024>>>(W1, W2, Wih, Whh);
    place_kernel<<<(N_EDGES + 255) / 256, 256>>>(eidx);

    msg_kernel<<<(N_EDGES + 255) / 256, 256, MSG_SMEM_BYTES>>>(ea, b1, b2);

    for (int s = 0; s < NSTEPS; ++s) {
        gather_kernel<<<(N_NODES * 8 + 255) / 256, 256>>>(h);
        gru_kernel<<<152, 512, GRU_SMEM_BYTES>>>(bih, bhh, h);
    }
}